// round 1
// baseline (speedup 1.0000x reference)
#include <cuda_runtime.h>

// Matern-3/2 Gram: out[n,m] = sigma^2 * (1+v) * exp(-v),
//   v = sqrt(3) * sqrt(max(|x_n|^2 + |z_m|^2 - 2 x_n.z_m, 1e-12)) / lengthscale
// Shapes: X[8192,64] f32, Z[4096,64] f32, out[8192,4096] f32.

#define SQRT3F 1.7320508075688772f

constexpr int KD  = 64;    // feature dim
constexpr int BM  = 128;   // X rows per block
constexpr int BN  = 128;   // Z rows per block
constexpr int PAD = 65;    // smem row pitch (odd -> conflict-free strided reads)

// scratch for row squared-norms: first N entries = |x_n|^2, next M = |z_m|^2
__device__ float g_rowsq[8192 + 4096];

__global__ void rowsq_kernel(const float* __restrict__ X,
                             const float* __restrict__ Z,
                             int N, int M) {
    int i = blockIdx.x * blockDim.x + threadIdx.x;
    int total = N + M;
    if (i >= total) return;
    const float* row = (i < N) ? (X + (size_t)i * KD)
                               : (Z + (size_t)(i - N) * KD);
    const float4* r4 = (const float4*)row;
    float s = 0.f;
#pragma unroll
    for (int k = 0; k < KD / 4; k++) {
        float4 v = r4[k];
        s += v.x * v.x + v.y * v.y + v.z * v.z + v.w * v.w;
    }
    g_rowsq[i] = s;
}

__global__ __launch_bounds__(256) void matern_kernel(
    const float* __restrict__ X, const float* __restrict__ Z,
    const float* __restrict__ sigma, const float* __restrict__ lengthscale,
    float* __restrict__ out, int N, int M)
{
    extern __shared__ float smem[];
    float* Xs = smem;                 // [BM][PAD]
    float* Zs = smem + BM * PAD;      // [BN][PAD]

    const int tid = threadIdx.x;
    const int tx  = tid & 15;         // 0..15 -> Z cols (stride 16)
    const int ty  = tid >> 4;         // 0..15 -> X rows (stride 16)
    const int brow = blockIdx.y * BM;
    const int bcol = blockIdx.x * BN;

    // ---- load tiles (X: BM x 64, Z: BN x 64), vectorized gmem, scalar smem stores ----
    const float4* Xg = (const float4*)(X + (size_t)brow * KD);
    const float4* Zg = (const float4*)(Z + (size_t)bcol * KD);
#pragma unroll
    for (int t = 0; t < (BM * KD / 4) / 256; t++) {   // 8 iterations
        int li = tid + t * 256;       // 0..2047
        int r  = li >> 4;             // row 0..127
        int kq = li & 15;             // float4 index in row
        float4 vx = Xg[(size_t)r * (KD / 4) + kq];
        float4 vz = Zg[(size_t)r * (KD / 4) + kq];
        float* xd = &Xs[r * PAD + kq * 4];
        xd[0] = vx.x; xd[1] = vx.y; xd[2] = vx.z; xd[3] = vx.w;
        float* zd = &Zs[r * PAD + kq * 4];
        zd[0] = vz.x; zd[1] = vz.y; zd[2] = vz.z; zd[3] = vz.w;
    }
    __syncthreads();

    // ---- 8x8 microtile dot-products over full K=64 ----
    float acc[8][8];
#pragma unroll
    for (int i = 0; i < 8; i++)
#pragma unroll
        for (int j = 0; j < 8; j++) acc[i][j] = 0.f;

#pragma unroll 4
    for (int k = 0; k < KD; k++) {
        float a[8], b[8];
#pragma unroll
        for (int i = 0; i < 8; i++) a[i] = Xs[(ty + 16 * i) * PAD + k];
#pragma unroll
        for (int j = 0; j < 8; j++) b[j] = Zs[(tx + 16 * j) * PAD + k];
#pragma unroll
        for (int i = 0; i < 8; i++)
#pragma unroll
            for (int j = 0; j < 8; j++)
                acc[i][j] += a[i] * b[j];
    }

    // ---- fused Matern-3/2 epilogue ----
    float sg = sigma[0];
    float s2 = sg * sg;
    float kv = SQRT3F / lengthscale[0];

    float x2[8], z2[8];
#pragma unroll
    for (int i = 0; i < 8; i++) x2[i] = g_rowsq[brow + ty + 16 * i];
#pragma unroll
    for (int j = 0; j < 8; j++) z2[j] = g_rowsq[N + bcol + tx + 16 * j];

#pragma unroll
    for (int i = 0; i < 8; i++) {
        size_t rowoff = (size_t)(brow + ty + 16 * i) * (size_t)M + bcol;
#pragma unroll
        for (int j = 0; j < 8; j++) {
            float sq = x2[i] + z2[j] - 2.0f * acc[i][j];
            sq = fmaxf(sq, 1e-12f);
            float dist = sqrtf(sq);
            float v = kv * dist;
            out[rowoff + tx + 16 * j] = s2 * (1.0f + v) * __expf(-v);
        }
    }
}

extern "C" void kernel_launch(void* const* d_in, const int* in_sizes, int n_in,
                              void* d_out, int out_size) {
    const float* X   = (const float*)d_in[0];
    const float* Z   = (const float*)d_in[1];
    const float* sig = (const float*)d_in[2];
    const float* len = (const float*)d_in[3];
    float* out = (float*)d_out;

    int N = in_sizes[0] / KD;   // 8192
    int M = in_sizes[1] / KD;   // 4096

    int total = N + M;
    rowsq_kernel<<<(total + 255) / 256, 256>>>(X, Z, N, M);

    size_t smem_bytes = (size_t)(BM + BN) * PAD * sizeof(float);  // 66560
    cudaFuncSetAttribute(matern_kernel,
                         cudaFuncAttributeMaxDynamicSharedMemorySize,
                         (int)smem_bytes);
    dim3 grid(M / BN, N / BM);
    matern_kernel<<<grid, 256, smem_bytes>>>(X, Z, sig, len, out, N, M);
}